// round 3
// baseline (speedup 1.0000x reference)
#include <cuda_runtime.h>
#include <cstdint>

#define NN 100000
#define EE 800000

// ---------------- scratch (__device__ globals; no allocation allowed) ----------
__device__ float g_deg[NN];                       // degree -> dinv_sqrt (in place)
__device__ __align__(16) float g_agg[NN * 128];   // aggregated X (layer-1 input to GEMM)
__device__ __align__(16) float g_h2[NN * 40];     // hidden @ W2 (pre-aggregation)

// ---------------- small helpers ------------------------------------------------
__device__ __forceinline__ unsigned long long pack2(float x, float y) {
    unsigned long long r;
    asm("mov.b64 %0, {%1, %2};" : "=l"(r) : "f"(x), "f"(y));
    return r;
}
__device__ __forceinline__ float2 unpack2(unsigned long long v) {
    float2 r;
    asm("mov.b64 {%0, %1}, %2;" : "=f"(r.x), "=f"(r.y) : "l"(v));
    return r;
}
__device__ __forceinline__ unsigned long long fma2(unsigned long long a,
                                                   unsigned long long b,
                                                   unsigned long long c) {
    unsigned long long d;
    asm("fma.rn.f32x2 %0, %1, %2, %3;" : "=l"(d) : "l"(a), "l"(b), "l"(c));
    return d;
}
__device__ __forceinline__ void red4(float* p, float a, float b, float c, float d) {
    asm volatile("red.global.add.v4.f32 [%0], {%1,%2,%3,%4};"
                 :: "l"(p), "f"(a), "f"(b), "f"(c), "f"(d) : "memory");
}

// JAX threefry2x32 with key = (0, 42)  [jax.random.key(42)]
__device__ __forceinline__ void threefry42(unsigned& x0, unsigned& x1) {
    const unsigned ks0 = 0u, ks1 = 42u, ks2 = 0x1BD11BDAu ^ 42u;
    x0 += ks0; x1 += ks1;
#define TFR(r) { x0 += x1; x1 = (x1 << (r)) | (x1 >> (32 - (r))); x1 ^= x0; }
    TFR(13) TFR(15) TFR(26) TFR(6)   x0 += ks1; x1 += ks2 + 1u;
    TFR(17) TFR(29) TFR(16) TFR(24)  x0 += ks2; x1 += ks0 + 2u;
    TFR(13) TFR(15) TFR(26) TFR(6)   x0 += ks0; x1 += ks1 + 3u;
    TFR(17) TFR(29) TFR(16) TFR(24)  x0 += ks1; x1 += ks2 + 4u;
    TFR(13) TFR(15) TFR(26) TFR(6)   x0 += ks2; x1 += ks0 + 5u;
#undef TFR
}

// keep-bit for dropout element with linear index idx (partitionable threefry):
// counter=(0, idx), bits = out0 ^ out1, keep <=> MSB(bits)==0.
__device__ __forceinline__ unsigned tf_bit(unsigned idx) {
    unsigned x0 = 0u, x1 = idx;
    threefry42(x0, x1);
    return (~(x0 ^ x1)) >> 31;
}

// ---------------- degree / normalization --------------------------------------
__global__ void deg_init_kernel() {
    int i = blockIdx.x * blockDim.x + threadIdx.x;
    if (i < NN) g_deg[i] = 1.0f;   // self loop
}
__global__ void deg_scatter_kernel(const int* __restrict__ dst) {
    int e = blockIdx.x * blockDim.x + threadIdx.x;
    if (e < EE) atomicAdd(&g_deg[dst[e]], 1.0f);
}
__global__ void deg_fin_kernel() {
    int i = blockIdx.x * blockDim.x + threadIdx.x;
    if (i < NN) g_deg[i] = rsqrtf(g_deg[i]);   // now holds dinv_sqrt
}

// ---------------- layer-1 aggregation: g_agg = D^-1/2 (A+I) D^-1/2 X -----------
__global__ void agg1_init_kernel(const float* __restrict__ x) {
    int gid = blockIdx.x * blockDim.x + threadIdx.x;   // over NN*32 float4s
    if (gid >= NN * 32) return;
    int node = gid >> 5;
    float di = g_deg[node];
    float s = di * di;
    float4 v = reinterpret_cast<const float4*>(x)[gid];
    float4 o = make_float4(v.x * s, v.y * s, v.z * s, v.w * s);
    reinterpret_cast<float4*>(g_agg)[gid] = o;
}
__global__ void agg1_scatter_kernel(const float* __restrict__ x,
                                    const int* __restrict__ src,
                                    const int* __restrict__ dst) {
    int gid = blockIdx.x * blockDim.x + threadIdx.x;
    int e = gid >> 5, lane = gid & 31;
    if (e >= EE) return;
    int s = src[e], d = dst[e];
    float nrm = g_deg[s] * g_deg[d];
    float4 v = *reinterpret_cast<const float4*>(&x[s * 128 + lane * 4]);
    red4(&g_agg[d * 128 + lane * 4], v.x * nrm, v.y * nrm, v.z * nrm, v.w * nrm);
}

// ---------------- GEMM1: H = relu(g_agg @ W1 + b1) * dropout (mask fused) ------
// 128x128 block tile, 256 threads, 8x8 thread tile, packed f32x2 FMA.
// The 64 threefry keep-bits per thread are computed interleaved with the FMA
// main loop (8 evals -> 16 k-steps -> 8 evals -> 16 k-steps per kc), so the
// alu-pipe threefry chains dual-issue under the fma-pipe FFMA2 stream.
__global__ __launch_bounds__(256) void gemm1_kernel(const float* __restrict__ W,
                                                    const float* __restrict__ bias,
                                                    float* __restrict__ H) {
    __shared__ __align__(16) float As[32][132];   // [k][m]
    __shared__ __align__(16) float Bs[32][128];   // [k][n]
    const int t = threadIdx.x;
    const int tx = t & 15, ty = t >> 4;
    const int m0 = blockIdx.x * 128;
    const int n0 = blockIdx.y * 128;

    unsigned long long acc[8][4];
#pragma unroll
    for (int i = 0; i < 8; i++)
#pragma unroll
        for (int j = 0; j < 4; j++) acc[i][j] = 0ull;

    unsigned mbits0 = 0u, mbits1 = 0u;            // 32 keep-bits per col-group
    const unsigned colbase0 = (unsigned)(n0 + tx * 4);
    const unsigned colbase1 = (unsigned)(n0 + 64 + tx * 4);

    const int am = t >> 3;    // 0..31 row-in-pass (A load)
    const int akq = t & 7;    // float4 index in k (A load)
    const int wk = t >> 5;    // 0..7 k-row-in-pass (W load)
    const int wn = t & 31;    // float4 col (W load)

#pragma unroll
    for (int kc = 0; kc < 4; kc++) {
        // A tile (transposed into As[k][m])
#pragma unroll
        for (int p = 0; p < 4; p++) {
            int m = p * 32 + am;
            int gr = m0 + m;
            float4 v = make_float4(0.f, 0.f, 0.f, 0.f);
            if (gr < NN)
                v = *reinterpret_cast<const float4*>(&g_agg[gr * 128 + kc * 32 + akq * 4]);
            As[akq * 4 + 0][m] = v.x;
            As[akq * 4 + 1][m] = v.y;
            As[akq * 4 + 2][m] = v.z;
            As[akq * 4 + 3][m] = v.w;
        }
        // W tile
#pragma unroll
        for (int p = 0; p < 4; p++) {
            int k = p * 8 + wk;
            *reinterpret_cast<float4*>(&Bs[k][wn * 4]) =
                *reinterpret_cast<const float4*>(&W[(kc * 32 + k) * 512 + n0 + wn * 4]);
        }
        __syncthreads();

        // two rows of mask bits this kc (row indices 2*kc and 2*kc+1 in the 8-row tile)
        const int i0 = 2 * kc, i1 = 2 * kc + 1;
        const int rl0 = (i0 < 4) ? (ty * 4 + i0) : (64 + ty * 4 + (i0 - 4));
        const int rl1 = (i1 < 4) ? (ty * 4 + i1) : (64 + ty * 4 + (i1 - 4));
        const unsigned b00 = (unsigned)(m0 + rl0) * 512u + colbase0;
        const unsigned b01 = (unsigned)(m0 + rl0) * 512u + colbase1;
        const unsigned b10 = (unsigned)(m0 + rl1) * 512u + colbase0;
        const unsigned b11 = (unsigned)(m0 + rl1) * 512u + colbase1;

        // batch 1: 8 threefry evals (row i0), interleaves with first 16 k-steps
#pragma unroll
        for (int b = 0; b < 4; b++) {
            mbits0 |= tf_bit(b00 + b) << (i0 * 4 + b);
            mbits1 |= tf_bit(b01 + b) << (i0 * 4 + b);
        }
#pragma unroll
        for (int k = 0; k < 16; k++) {
            float4 a0 = *reinterpret_cast<const float4*>(&As[k][ty * 4]);
            float4 a1 = *reinterpret_cast<const float4*>(&As[k][ty * 4 + 64]);
            ulonglong2 bb0 = *reinterpret_cast<const ulonglong2*>(&Bs[k][tx * 4]);
            ulonglong2 bb1 = *reinterpret_cast<const ulonglong2*>(&Bs[k][tx * 4 + 64]);
            unsigned long long ad[8];
            ad[0] = pack2(a0.x, a0.x); ad[1] = pack2(a0.y, a0.y);
            ad[2] = pack2(a0.z, a0.z); ad[3] = pack2(a0.w, a0.w);
            ad[4] = pack2(a1.x, a1.x); ad[5] = pack2(a1.y, a1.y);
            ad[6] = pack2(a1.z, a1.z); ad[7] = pack2(a1.w, a1.w);
#pragma unroll
            for (int i = 0; i < 8; i++) {
                acc[i][0] = fma2(ad[i], bb0.x, acc[i][0]);
                acc[i][1] = fma2(ad[i], bb0.y, acc[i][1]);
                acc[i][2] = fma2(ad[i], bb1.x, acc[i][2]);
                acc[i][3] = fma2(ad[i], bb1.y, acc[i][3]);
            }
        }
        // batch 2: 8 threefry evals (row i1), interleaves with last 16 k-steps
#pragma unroll
        for (int b = 0; b < 4; b++) {
            mbits0 |= tf_bit(b10 + b) << (i1 * 4 + b);
            mbits1 |= tf_bit(b11 + b) << (i1 * 4 + b);
        }
#pragma unroll
        for (int k = 16; k < 32; k++) {
            float4 a0 = *reinterpret_cast<const float4*>(&As[k][ty * 4]);
            float4 a1 = *reinterpret_cast<const float4*>(&As[k][ty * 4 + 64]);
            ulonglong2 bb0 = *reinterpret_cast<const ulonglong2*>(&Bs[k][tx * 4]);
            ulonglong2 bb1 = *reinterpret_cast<const ulonglong2*>(&Bs[k][tx * 4 + 64]);
            unsigned long long ad[8];
            ad[0] = pack2(a0.x, a0.x); ad[1] = pack2(a0.y, a0.y);
            ad[2] = pack2(a0.z, a0.z); ad[3] = pack2(a0.w, a0.w);
            ad[4] = pack2(a1.x, a1.x); ad[5] = pack2(a1.y, a1.y);
            ad[6] = pack2(a1.z, a1.z); ad[7] = pack2(a1.w, a1.w);
#pragma unroll
            for (int i = 0; i < 8; i++) {
                acc[i][0] = fma2(ad[i], bb0.x, acc[i][0]);
                acc[i][1] = fma2(ad[i], bb0.y, acc[i][1]);
                acc[i][2] = fma2(ad[i], bb1.x, acc[i][2]);
                acc[i][3] = fma2(ad[i], bb1.y, acc[i][3]);
            }
        }
        __syncthreads();
    }

    // epilogue: bias + relu + dropout (fused mask bits) -> H
    float4 bias0 = *reinterpret_cast<const float4*>(&bias[n0 + tx * 4]);
    float4 bias1 = *reinterpret_cast<const float4*>(&bias[n0 + 64 + tx * 4]);
#pragma unroll
    for (int i = 0; i < 8; i++) {
        int rl = (i < 4) ? (ty * 4 + i) : (64 + ty * 4 + (i - 4));
        int row = m0 + rl;
        if (row >= NN) continue;
        unsigned mw0 = mbits0 >> (i * 4);
        unsigned mw1 = mbits1 >> (i * 4);
        float2 c0 = unpack2(acc[i][0]);
        float2 c1 = unpack2(acc[i][1]);
        float2 c2 = unpack2(acc[i][2]);
        float2 c3 = unpack2(acc[i][3]);
        float4 o0, o1;
        o0.x = ((mw0 >> 0) & 1u) ? fmaxf(c0.x + bias0.x, 0.f) * 2.f : 0.f;
        o0.y = ((mw0 >> 1) & 1u) ? fmaxf(c0.y + bias0.y, 0.f) * 2.f : 0.f;
        o0.z = ((mw0 >> 2) & 1u) ? fmaxf(c1.x + bias0.z, 0.f) * 2.f : 0.f;
        o0.w = ((mw0 >> 3) & 1u) ? fmaxf(c1.y + bias0.w, 0.f) * 2.f : 0.f;
        o1.x = ((mw1 >> 0) & 1u) ? fmaxf(c2.x + bias1.x, 0.f) * 2.f : 0.f;
        o1.y = ((mw1 >> 1) & 1u) ? fmaxf(c2.y + bias1.y, 0.f) * 2.f : 0.f;
        o1.z = ((mw1 >> 2) & 1u) ? fmaxf(c3.x + bias1.z, 0.f) * 2.f : 0.f;
        o1.w = ((mw1 >> 3) & 1u) ? fmaxf(c3.y + bias1.w, 0.f) * 2.f : 0.f;
        *reinterpret_cast<float4*>(&H[row * 512 + n0 + tx * 4]) = o0;
        *reinterpret_cast<float4*>(&H[row * 512 + n0 + 64 + tx * 4]) = o1;
    }
}

// ---------------- GEMM2: g_h2 = H @ W2  (100000x512 @ 512x40) ------------------
__global__ __launch_bounds__(256) void gemm2_kernel(const float* __restrict__ H,
                                                    const float* __restrict__ W2) {
    __shared__ __align__(16) float As[32][260];
    __shared__ __align__(16) float Ws[32][40];
    const int t = threadIdx.x;
    const int rg = t & 63;        // row group 0..63
    const int cg = t >> 6;        // col group 0..3 (10 cols each)
    const int m0 = blockIdx.x * 256;

    unsigned long long acc[4][5];
#pragma unroll
    for (int i = 0; i < 4; i++)
#pragma unroll
        for (int j = 0; j < 5; j++) acc[i][j] = 0ull;

    const int akq = t & 7;
    const int am = t >> 3;   // 0..31 per pass

    for (int kc = 0; kc < 16; kc++) {
#pragma unroll
        for (int p = 0; p < 8; p++) {
            int m = p * 32 + am;
            int gr = m0 + m;
            float4 v = make_float4(0.f, 0.f, 0.f, 0.f);
            if (gr < NN)
                v = *reinterpret_cast<const float4*>(&H[gr * 512 + kc * 32 + akq * 4]);
            As[akq * 4 + 0][m] = v.x;
            As[akq * 4 + 1][m] = v.y;
            As[akq * 4 + 2][m] = v.z;
            As[akq * 4 + 3][m] = v.w;
        }
#pragma unroll
        for (int p = 0; p < 2; p++) {
            int idx = p * 256 + t;
            if (idx < 320) {
                int k = idx / 10, c = idx % 10;
                *reinterpret_cast<float4*>(&Ws[k][c * 4]) =
                    *reinterpret_cast<const float4*>(&W2[(kc * 32 + k) * 40 + c * 4]);
            }
        }
        __syncthreads();
#pragma unroll
        for (int k = 0; k < 32; k++) {
            float4 a = *reinterpret_cast<const float4*>(&As[k][rg * 4]);
            const float* wr = &Ws[k][cg * 10];
            unsigned long long w0 = *reinterpret_cast<const unsigned long long*>(wr + 0);
            unsigned long long w1 = *reinterpret_cast<const unsigned long long*>(wr + 2);
            unsigned long long w2 = *reinterpret_cast<const unsigned long long*>(wr + 4);
            unsigned long long w3 = *reinterpret_cast<const unsigned long long*>(wr + 6);
            unsigned long long w4 = *reinterpret_cast<const unsigned long long*>(wr + 8);
            float av[4] = {a.x, a.y, a.z, a.w};
#pragma unroll
            for (int i = 0; i < 4; i++) {
                unsigned long long ai = pack2(av[i], av[i]);
                acc[i][0] = fma2(ai, w0, acc[i][0]);
                acc[i][1] = fma2(ai, w1, acc[i][1]);
                acc[i][2] = fma2(ai, w2, acc[i][2]);
                acc[i][3] = fma2(ai, w3, acc[i][3]);
                acc[i][4] = fma2(ai, w4, acc[i][4]);
            }
        }
        __syncthreads();
    }
#pragma unroll
    for (int i = 0; i < 4; i++) {
        int row = m0 + rg * 4 + i;
        if (row >= NN) continue;
#pragma unroll
        for (int j = 0; j < 5; j++)
            *reinterpret_cast<unsigned long long*>(&g_h2[row * 40 + cg * 10 + j * 2]) = acc[i][j];
    }
}

// ---------------- layer-2 aggregation: out = Â g_h2 + b2 -----------------------
__global__ void agg2_init_kernel(const float* __restrict__ b2, float* __restrict__ out) {
    int gid = blockIdx.x * blockDim.x + threadIdx.x;   // over NN*10 float4s
    if (gid >= NN * 10) return;
    int node = gid / 10;
    int c = gid - node * 10;
    float di = g_deg[node];
    float s = di * di;
    float4 v = *reinterpret_cast<const float4*>(&g_h2[node * 40 + c * 4]);
    float4 bb = *reinterpret_cast<const float4*>(&b2[c * 4]);
    float4 o = make_float4(bb.x + v.x * s, bb.y + v.y * s, bb.z + v.z * s, bb.w + v.w * s);
    *reinterpret_cast<float4*>(&out[node * 40 + c * 4]) = o;
}
__global__ void agg2_scatter_kernel(const int* __restrict__ src,
                                    const int* __restrict__ dst,
                                    float* __restrict__ out) {
    int gid = blockIdx.x * blockDim.x + threadIdx.x;   // EE*10
    int e = gid / 10;
    int c = gid - e * 10;
    if (e >= EE) return;
    int s = src[e], d = dst[e];
    float nrm = g_deg[s] * g_deg[d];
    float4 v = *reinterpret_cast<const float4*>(&g_h2[s * 40 + c * 4]);
    red4(&out[d * 40 + c * 4], v.x * nrm, v.y * nrm, v.z * nrm, v.w * nrm);
}

// ---------------- launch --------------------------------------------------------
extern "C" void kernel_launch(void* const* d_in, const int* in_sizes, int n_in,
                              void* d_out, int out_size) {
    const float* x  = (const float*)d_in[0];
    const int*   ei = (const int*)d_in[1];
    const float* W1 = (const float*)d_in[2];
    const float* b1 = (const float*)d_in[3];
    const float* W2 = (const float*)d_in[4];
    const float* b2 = (const float*)d_in[5];
    (void)in_sizes; (void)n_in; (void)out_size;

    float* out = (float*)d_out;           // [NN, 40]
    float* hidden = out + NN * 40;        // [NN, 512]
    const int* src = ei;
    const int* dst = ei + EE;

    deg_init_kernel<<<(NN + 255) / 256, 256>>>();
    deg_scatter_kernel<<<(EE + 255) / 256, 256>>>(dst);
    deg_fin_kernel<<<(NN + 255) / 256, 256>>>();

    agg1_init_kernel<<<(NN * 32) / 256, 256>>>(x);
    agg1_scatter_kernel<<<(EE * 32) / 256, 256>>>(x, src, dst);

    gemm1_kernel<<<dim3((NN + 127) / 128, 4), 256>>>(W1, b1, hidden);
    gemm2_kernel<<<(NN + 255) / 256, 256>>>(hidden, W2);

    agg2_init_kernel<<<(NN * 10 + 255) / 256, 256>>>(b2, out);
    agg2_scatter_kernel<<<(EE * 10) / 256, 256>>>(src, dst, out);
}

// round 4
// speedup vs baseline: 1.7289x; 1.7289x over previous
#include <cuda_runtime.h>
#include <cstdint>

#define NN 100000
#define EE 800000

// ---------------- scratch (__device__ globals; no allocation allowed) ----------
__device__ float g_deg[NN];                       // degree -> dinv_sqrt (in place)
__device__ __align__(16) float g_agg[NN * 128];   // aggregated X (layer-1 input to GEMM)
__device__ __align__(16) float g_h2[NN * 40];     // hidden @ W2 (pre-aggregation)
__device__ unsigned g_mask[1600000];              // 51.2M dropout keep-bits

// ---------------- small helpers ------------------------------------------------
__device__ __forceinline__ unsigned long long pack2(float x, float y) {
    unsigned long long r;
    asm("mov.b64 %0, {%1, %2};" : "=l"(r) : "f"(x), "f"(y));
    return r;
}
__device__ __forceinline__ float2 unpack2(unsigned long long v) {
    float2 r;
    asm("mov.b64 {%0, %1}, %2;" : "=f"(r.x), "=f"(r.y) : "l"(v));
    return r;
}
__device__ __forceinline__ unsigned long long fma2(unsigned long long a,
                                                   unsigned long long b,
                                                   unsigned long long c) {
    unsigned long long d;
    asm("fma.rn.f32x2 %0, %1, %2, %3;" : "=l"(d) : "l"(a), "l"(b), "l"(c));
    return d;
}
__device__ __forceinline__ void red4(float* p, float a, float b, float c, float d) {
    asm volatile("red.global.add.v4.f32 [%0], {%1,%2,%3,%4};"
                 :: "l"(p), "f"(a), "f"(b), "f"(c), "f"(d) : "memory");
}

// JAX threefry2x32 with key = (0, 42)  [jax.random.key(42)]
__device__ __forceinline__ void threefry42(unsigned& x0, unsigned& x1) {
    const unsigned ks0 = 0u, ks1 = 42u, ks2 = 0x1BD11BDAu ^ 42u;
    x0 += ks0; x1 += ks1;
#define TFR(r) { x0 += x1; x1 = (x1 << (r)) | (x1 >> (32 - (r))); x1 ^= x0; }
    TFR(13) TFR(15) TFR(26) TFR(6)   x0 += ks1; x1 += ks2 + 1u;
    TFR(17) TFR(29) TFR(16) TFR(24)  x0 += ks2; x1 += ks0 + 2u;
    TFR(13) TFR(15) TFR(26) TFR(6)   x0 += ks0; x1 += ks1 + 3u;
    TFR(17) TFR(29) TFR(16) TFR(24)  x0 += ks1; x1 += ks2 + 4u;
    TFR(13) TFR(15) TFR(26) TFR(6)   x0 += ks2; x1 += ks0 + 5u;
#undef TFR
}

// keep-bit for dropout element idx (JAX partitionable threefry):
// counter=(0, idx), bits = out0 ^ out1, keep <=> MSB(bits)==0.
__device__ __forceinline__ unsigned tf_bit(unsigned idx) {
    unsigned x0 = 0u, x1 = idx;
    threefry42(x0, x1);
    return (~(x0 ^ x1)) >> 31;
}

// ---------------- degree / normalization --------------------------------------
__global__ void deg_init_kernel() {
    int i = blockIdx.x * blockDim.x + threadIdx.x;
    if (i < NN) g_deg[i] = 1.0f;   // self loop
}
__global__ void deg_scatter_kernel(const int* __restrict__ dst) {
    int e = blockIdx.x * blockDim.x + threadIdx.x;
    if (e < EE) atomicAdd(&g_deg[dst[e]], 1.0f);
}
__global__ void deg_fin_kernel() {
    int i = blockIdx.x * blockDim.x + threadIdx.x;
    if (i < NN) g_deg[i] = rsqrtf(g_deg[i]);   // now holds dinv_sqrt
}

// ---------------- layer-1 aggregation: g_agg = D^-1/2 (A+I) D^-1/2 X -----------
__global__ void agg1_init_kernel(const float* __restrict__ x) {
    int gid = blockIdx.x * blockDim.x + threadIdx.x;   // over NN*32 float4s
    if (gid >= NN * 32) return;
    int node = gid >> 5;
    float di = g_deg[node];
    float s = di * di;
    float4 v = reinterpret_cast<const float4*>(x)[gid];
    float4 o = make_float4(v.x * s, v.y * s, v.z * s, v.w * s);
    reinterpret_cast<float4*>(g_agg)[gid] = o;
}

// Scatter + fused dropout-mask generation.
// Warp e (= gid>>5) also computes mask words 2e and 2e+1: each lane evaluates
// threefry for element indices 64e+lane and 64e+32+lane; __ballot_sync packs
// the 32 keep-bits in lane order (bit j = lane j), lane 0 stores the words.
// The ~140 ALU ops/thread issue under the scatter's long-scoreboard stalls.
__global__ void agg1_scatter_kernel(const float* __restrict__ x,
                                    const int* __restrict__ src,
                                    const int* __restrict__ dst) {
    int gid = blockIdx.x * blockDim.x + threadIdx.x;   // exactly EE*32 threads
    int e = gid >> 5, lane = gid & 31;

    // fused mask generation (covers all 51.2M bits exactly)
    unsigned base = (unsigned)e * 64u + (unsigned)lane;
    unsigned bit0 = tf_bit(base);
    unsigned bit1 = tf_bit(base + 32u);
    unsigned w0 = __ballot_sync(0xFFFFFFFFu, bit0);
    unsigned w1 = __ballot_sync(0xFFFFFFFFu, bit1);
    if (lane == 0) {
        g_mask[2 * e]     = w0;
        g_mask[2 * e + 1] = w1;
    }

    // edge scatter
    int s = src[e], d = dst[e];
    float nrm = g_deg[s] * g_deg[d];
    float4 v = *reinterpret_cast<const float4*>(&x[s * 128 + lane * 4]);
    red4(&g_agg[d * 128 + lane * 4], v.x * nrm, v.y * nrm, v.z * nrm, v.w * nrm);
}

// ---------------- GEMM1: H = relu(g_agg @ W1 + b1) * dropout ------------------
// 128x128 block tile, 256 threads, 8x8 thread tile, packed f32x2 FMA.
__global__ __launch_bounds__(256) void gemm1_kernel(const float* __restrict__ W,
                                                    const float* __restrict__ bias,
                                                    float* __restrict__ H) {
    __shared__ __align__(16) float As[32][132];   // [k][m]
    __shared__ __align__(16) float Bs[32][128];   // [k][n]
    const int t = threadIdx.x;
    const int tx = t & 15, ty = t >> 4;
    const int m0 = blockIdx.x * 128;
    const int n0 = blockIdx.y * 128;

    unsigned long long acc[8][4];
#pragma unroll
    for (int i = 0; i < 8; i++)
#pragma unroll
        for (int j = 0; j < 4; j++) acc[i][j] = 0ull;

    const int am = t >> 3;    // 0..31 row-in-pass (A load)
    const int akq = t & 7;    // float4 index in k (A load)
    const int wk = t >> 5;    // 0..7 k-row-in-pass (W load)
    const int wn = t & 31;    // float4 col (W load)

    for (int kc = 0; kc < 4; kc++) {
        // A tile (transposed into As[k][m])
#pragma unroll
        for (int p = 0; p < 4; p++) {
            int m = p * 32 + am;
            int gr = m0 + m;
            float4 v = make_float4(0.f, 0.f, 0.f, 0.f);
            if (gr < NN)
                v = *reinterpret_cast<const float4*>(&g_agg[gr * 128 + kc * 32 + akq * 4]);
            As[akq * 4 + 0][m] = v.x;
            As[akq * 4 + 1][m] = v.y;
            As[akq * 4 + 2][m] = v.z;
            As[akq * 4 + 3][m] = v.w;
        }
        // W tile
#pragma unroll
        for (int p = 0; p < 4; p++) {
            int k = p * 8 + wk;
            *reinterpret_cast<float4*>(&Bs[k][wn * 4]) =
                *reinterpret_cast<const float4*>(&W[(kc * 32 + k) * 512 + n0 + wn * 4]);
        }
        __syncthreads();
#pragma unroll
        for (int k = 0; k < 32; k++) {
            float4 a0 = *reinterpret_cast<const float4*>(&As[k][ty * 4]);
            float4 a1 = *reinterpret_cast<const float4*>(&As[k][ty * 4 + 64]);
            ulonglong2 b0 = *reinterpret_cast<const ulonglong2*>(&Bs[k][tx * 4]);
            ulonglong2 b1 = *reinterpret_cast<const ulonglong2*>(&Bs[k][tx * 4 + 64]);
            unsigned long long ad[8];
            ad[0] = pack2(a0.x, a0.x); ad[1] = pack2(a0.y, a0.y);
            ad[2] = pack2(a0.z, a0.z); ad[3] = pack2(a0.w, a0.w);
            ad[4] = pack2(a1.x, a1.x); ad[5] = pack2(a1.y, a1.y);
            ad[6] = pack2(a1.z, a1.z); ad[7] = pack2(a1.w, a1.w);
#pragma unroll
            for (int i = 0; i < 8; i++) {
                acc[i][0] = fma2(ad[i], b0.x, acc[i][0]);
                acc[i][1] = fma2(ad[i], b0.y, acc[i][1]);
                acc[i][2] = fma2(ad[i], b1.x, acc[i][2]);
                acc[i][3] = fma2(ad[i], b1.y, acc[i][3]);
            }
        }
        __syncthreads();
    }

    // epilogue: bias + relu + dropout (mask bits) -> H
    float4 bias0 = *reinterpret_cast<const float4*>(&bias[n0 + tx * 4]);
    float4 bias1 = *reinterpret_cast<const float4*>(&bias[n0 + 64 + tx * 4]);
    const int w0i = (n0 + tx * 4) >> 5;
    const int w1i = (n0 + 64 + tx * 4) >> 5;
    const int sh = (tx * 4) & 31;
#pragma unroll
    for (int i = 0; i < 8; i++) {
        int rl = (i < 4) ? (ty * 4 + i) : (64 + ty * 4 + (i - 4));
        int row = m0 + rl;
        if (row >= NN) continue;
        unsigned mw0 = g_mask[row * 16 + w0i];
        unsigned mw1 = g_mask[row * 16 + w1i];
        float2 c0 = unpack2(acc[i][0]);
        float2 c1 = unpack2(acc[i][1]);
        float2 c2 = unpack2(acc[i][2]);
        float2 c3 = unpack2(acc[i][3]);
        float4 o0, o1;
        o0.x = ((mw0 >> (sh + 0)) & 1u) ? fmaxf(c0.x + bias0.x, 0.f) * 2.f : 0.f;
        o0.y = ((mw0 >> (sh + 1)) & 1u) ? fmaxf(c0.y + bias0.y, 0.f) * 2.f : 0.f;
        o0.z = ((mw0 >> (sh + 2)) & 1u) ? fmaxf(c1.x + bias0.z, 0.f) * 2.f : 0.f;
        o0.w = ((mw0 >> (sh + 3)) & 1u) ? fmaxf(c1.y + bias0.w, 0.f) * 2.f : 0.f;
        o1.x = ((mw1 >> (sh + 0)) & 1u) ? fmaxf(c2.x + bias1.x, 0.f) * 2.f : 0.f;
        o1.y = ((mw1 >> (sh + 1)) & 1u) ? fmaxf(c2.y + bias1.y, 0.f) * 2.f : 0.f;
        o1.z = ((mw1 >> (sh + 2)) & 1u) ? fmaxf(c3.x + bias1.z, 0.f) * 2.f : 0.f;
        o1.w = ((mw1 >> (sh + 3)) & 1u) ? fmaxf(c3.y + bias1.w, 0.f) * 2.f : 0.f;
        *reinterpret_cast<float4*>(&H[row * 512 + n0 + tx * 4]) = o0;
        *reinterpret_cast<float4*>(&H[row * 512 + n0 + 64 + tx * 4]) = o1;
    }
}

// ---------------- GEMM2: g_h2 = H @ W2  (100000x512 @ 512x40) ------------------
__global__ __launch_bounds__(256) void gemm2_kernel(const float* __restrict__ H,
                                                    const float* __restrict__ W2) {
    __shared__ __align__(16) float As[32][260];
    __shared__ __align__(16) float Ws[32][40];
    const int t = threadIdx.x;
    const int rg = t & 63;        // row group 0..63
    const int cg = t >> 6;        // col group 0..3 (10 cols each)
    const int m0 = blockIdx.x * 256;

    unsigned long long acc[4][5];
#pragma unroll
    for (int i = 0; i < 4; i++)
#pragma unroll
        for (int j = 0; j < 5; j++) acc[i][j] = 0ull;

    const int akq = t & 7;
    const int am = t >> 3;   // 0..31 per pass

    for (int kc = 0; kc < 16; kc++) {
#pragma unroll
        for (int p = 0; p < 8; p++) {
            int m = p * 32 + am;
            int gr = m0 + m;
            float4 v = make_float4(0.f, 0.f, 0.f, 0.f);
            if (gr < NN)
                v = *reinterpret_cast<const float4*>(&H[gr * 512 + kc * 32 + akq * 4]);
            As[akq * 4 + 0][m] = v.x;
            As[akq * 4 + 1][m] = v.y;
            As[akq * 4 + 2][m] = v.z;
            As[akq * 4 + 3][m] = v.w;
        }
#pragma unroll
        for (int p = 0; p < 2; p++) {
            int idx = p * 256 + t;
            if (idx < 320) {
                int k = idx / 10, c = idx % 10;
                *reinterpret_cast<float4*>(&Ws[k][c * 4]) =
                    *reinterpret_cast<const float4*>(&W2[(kc * 32 + k) * 40 + c * 4]);
            }
        }
        __syncthreads();
#pragma unroll
        for (int k = 0; k < 32; k++) {
            float4 a = *reinterpret_cast<const float4*>(&As[k][rg * 4]);
            const float* wr = &Ws[k][cg * 10];
            unsigned long long w0 = *reinterpret_cast<const unsigned long long*>(wr + 0);
            unsigned long long w1 = *reinterpret_cast<const unsigned long long*>(wr + 2);
            unsigned long long w2 = *reinterpret_cast<const unsigned long long*>(wr + 4);
            unsigned long long w3 = *reinterpret_cast<const unsigned long long*>(wr + 6);
            unsigned long long w4 = *reinterpret_cast<const unsigned long long*>(wr + 8);
            float av[4] = {a.x, a.y, a.z, a.w};
#pragma unroll
            for (int i = 0; i < 4; i++) {
                unsigned long long ai = pack2(av[i], av[i]);
                acc[i][0] = fma2(ai, w0, acc[i][0]);
                acc[i][1] = fma2(ai, w1, acc[i][1]);
                acc[i][2] = fma2(ai, w2, acc[i][2]);
                acc[i][3] = fma2(ai, w3, acc[i][3]);
                acc[i][4] = fma2(ai, w4, acc[i][4]);
            }
        }
        __syncthreads();
    }
#pragma unroll
    for (int i = 0; i < 4; i++) {
        int row = m0 + rg * 4 + i;
        if (row >= NN) continue;
#pragma unroll
        for (int j = 0; j < 5; j++)
            *reinterpret_cast<unsigned long long*>(&g_h2[row * 40 + cg * 10 + j * 2]) = acc[i][j];
    }
}

// ---------------- layer-2 aggregation: out = Â g_h2 + b2 -----------------------
__global__ void agg2_init_kernel(const float* __restrict__ b2, float* __restrict__ out) {
    int gid = blockIdx.x * blockDim.x + threadIdx.x;   // over NN*10 float4s
    if (gid >= NN * 10) return;
    int node = gid / 10;
    int c = gid - node * 10;
    float di = g_deg[node];
    float s = di * di;
    float4 v = *reinterpret_cast<const float4*>(&g_h2[node * 40 + c * 4]);
    float4 bb = *reinterpret_cast<const float4*>(&b2[c * 4]);
    float4 o = make_float4(bb.x + v.x * s, bb.y + v.y * s, bb.z + v.z * s, bb.w + v.w * s);
    *reinterpret_cast<float4*>(&out[node * 40 + c * 4]) = o;
}
__global__ void agg2_scatter_kernel(const int* __restrict__ src,
                                    const int* __restrict__ dst,
                                    float* __restrict__ out) {
    int gid = blockIdx.x * blockDim.x + threadIdx.x;   // EE*10
    int e = gid / 10;
    int c = gid - e * 10;
    if (e >= EE) return;
    int s = src[e], d = dst[e];
    float nrm = g_deg[s] * g_deg[d];
    float4 v = *reinterpret_cast<const float4*>(&g_h2[s * 40 + c * 4]);
    red4(&out[d * 40 + c * 4], v.x * nrm, v.y * nrm, v.z * nrm, v.w * nrm);
}

// ---------------- launch --------------------------------------------------------
extern "C" void kernel_launch(void* const* d_in, const int* in_sizes, int n_in,
                              void* d_out, int out_size) {
    const float* x  = (const float*)d_in[0];
    const int*   ei = (const int*)d_in[1];
    const float* W1 = (const float*)d_in[2];
    const float* b1 = (const float*)d_in[3];
    const float* W2 = (const float*)d_in[4];
    const float* b2 = (const float*)d_in[5];
    (void)in_sizes; (void)n_in; (void)out_size;

    float* out = (float*)d_out;           // [NN, 40]
    float* hidden = out + NN * 40;        // [NN, 512]
    const int* src = ei;
    const int* dst = ei + EE;

    deg_init_kernel<<<(NN + 255) / 256, 256>>>();
    deg_scatter_kernel<<<(EE + 255) / 256, 256>>>(dst);
    deg_fin_kernel<<<(NN + 255) / 256, 256>>>();

    agg1_init_kernel<<<(NN * 32) / 256, 256>>>(x);
    agg1_scatter_kernel<<<(EE * 32) / 256, 256>>>(x, src, dst);  // + fused mask

    gemm1_kernel<<<dim3((NN + 127) / 128, 4), 256>>>(W1, b1, hidden);
    gemm2_kernel<<<(NN + 255) / 256, 256>>>(hidden, W2);

    agg2_init_kernel<<<(NN * 10 + 255) / 256, 256>>>(b2, out);
    agg2_scatter_kernel<<<(EE * 10) / 256, 256>>>(src, dst, out);
}

// round 6
// speedup vs baseline: 1.8234x; 1.0546x over previous
#include <cuda_runtime.h>
#include <cuda_bf16.h>
#include <cstdint>

#define NN 100000
#define EE 800000

// ---------------- scratch (__device__ globals; no allocation allowed) ----------
__device__ float g_deg[NN];                       // degree -> dinv_sqrt (in place)
__device__ __align__(16) float g_agg[NN * 128];   // aggregated X (layer-1 GEMM input)
__device__ __align__(16) float g_h2[NN * 40];     // hidden @ W2 (pre-aggregation)
__device__ unsigned g_mask[1600000];              // 51.2M dropout keep-bits
// plain k-major bf16 images of W1 (hi/lo split): [k=128][n=512]
__device__ __align__(16) __nv_bfloat16 gBh[128 * 512];
__device__ __align__(16) __nv_bfloat16 gBl[128 * 512];

// ---------------- small helpers ------------------------------------------------
__device__ __forceinline__ unsigned long long pack2(float x, float y) {
    unsigned long long r;
    asm("mov.b64 %0, {%1, %2};" : "=l"(r) : "f"(x), "f"(y));
    return r;
}
__device__ __forceinline__ unsigned long long fma2(unsigned long long a,
                                                   unsigned long long b,
                                                   unsigned long long c) {
    unsigned long long d;
    asm("fma.rn.f32x2 %0, %1, %2, %3;" : "=l"(d) : "l"(a), "l"(b), "l"(c));
    return d;
}
__device__ __forceinline__ void red4(float* p, float a, float b, float c, float d) {
    asm volatile("red.global.add.v4.f32 [%0], {%1,%2,%3,%4};"
                 :: "l"(p), "f"(a), "f"(b), "f"(c), "f"(d) : "memory");
}
__device__ __forceinline__ unsigned smem_u32(const void* p) {
    unsigned a;
    asm("{ .reg .u64 t; cvta.to.shared.u64 t, %1; cvt.u32.u64 %0, t; }" : "=r"(a) : "l"(p));
    return a;
}

// JAX threefry2x32 with key = (0, 42)
__device__ __forceinline__ void threefry42(unsigned& x0, unsigned& x1) {
    const unsigned ks0 = 0u, ks1 = 42u, ks2 = 0x1BD11BDAu ^ 42u;
    x0 += ks0; x1 += ks1;
#define TFR(r) { x0 += x1; x1 = (x1 << (r)) | (x1 >> (32 - (r))); x1 ^= x0; }
    TFR(13) TFR(15) TFR(26) TFR(6)   x0 += ks1; x1 += ks2 + 1u;
    TFR(17) TFR(29) TFR(16) TFR(24)  x0 += ks2; x1 += ks0 + 2u;
    TFR(13) TFR(15) TFR(26) TFR(6)   x0 += ks0; x1 += ks1 + 3u;
    TFR(17) TFR(29) TFR(16) TFR(24)  x0 += ks1; x1 += ks2 + 4u;
    TFR(13) TFR(15) TFR(26) TFR(6)   x0 += ks2; x1 += ks0 + 5u;
#undef TFR
}
__device__ __forceinline__ unsigned tf_bit(unsigned idx) {
    unsigned x0 = 0u, x1 = idx;
    threefry42(x0, x1);
    return (~(x0 ^ x1)) >> 31;
}

// ---------------- mma.sync / ldmatrix wrappers (base ISA, no 'a' features) -----
__device__ __forceinline__ void mma_bf16(float* c, const unsigned* a, unsigned b0, unsigned b1) {
    asm volatile(
        "mma.sync.aligned.m16n8k16.row.col.f32.bf16.bf16.f32 "
        "{%0,%1,%2,%3}, {%4,%5,%6,%7}, {%8,%9}, {%0,%1,%2,%3};"
        : "+f"(c[0]), "+f"(c[1]), "+f"(c[2]), "+f"(c[3])
        : "r"(a[0]), "r"(a[1]), "r"(a[2]), "r"(a[3]), "r"(b0), "r"(b1));
}
__device__ __forceinline__ void ldsm_x4(unsigned* r, unsigned addr) {
    asm volatile("ldmatrix.sync.aligned.m8n8.x4.shared.b16 {%0,%1,%2,%3}, [%4];"
                 : "=r"(r[0]), "=r"(r[1]), "=r"(r[2]), "=r"(r[3]) : "r"(addr));
}
__device__ __forceinline__ void ldsm_x4t(unsigned* r, unsigned addr) {
    asm volatile("ldmatrix.sync.aligned.m8n8.x4.trans.shared.b16 {%0,%1,%2,%3}, [%4];"
                 : "=r"(r[0]), "=r"(r[1]), "=r"(r[2]), "=r"(r[3]) : "r"(addr));
}

// ---------------- degree / normalization --------------------------------------
__global__ void deg_init_kernel() {
    int i = blockIdx.x * blockDim.x + threadIdx.x;
    if (i < NN) g_deg[i] = 1.0f;
}
__global__ void deg_scatter_kernel(const int* __restrict__ dst) {
    int e = blockIdx.x * blockDim.x + threadIdx.x;
    if (e < EE) atomicAdd(&g_deg[dst[e]], 1.0f);
}
__global__ void deg_fin_kernel() {
    int i = blockIdx.x * blockDim.x + threadIdx.x;
    if (i < NN) g_deg[i] = rsqrtf(g_deg[i]);
}

// ---------------- W1 -> plain k-major bf16 split images ------------------------
__global__ void w1cvt_kernel(const float* __restrict__ W1) {
    int t = blockIdx.x * blockDim.x + threadIdx.x;   // 8192 threads, 8 elems each
    if (t >= 8192) return;
    int idx = t * 8;                                  // linear into [128][512]
    unsigned short h[8], l[8];
#pragma unroll
    for (int j = 0; j < 8; j++) {
        float v = W1[idx + j];
        __nv_bfloat16 bh = __float2bfloat16(v);
        __nv_bfloat16 bl = __float2bfloat16(v - __bfloat162float(bh));
        h[j] = *reinterpret_cast<unsigned short*>(&bh);
        l[j] = *reinterpret_cast<unsigned short*>(&bl);
    }
    uint4 ph = make_uint4((unsigned)h[0] | ((unsigned)h[1] << 16),
                          (unsigned)h[2] | ((unsigned)h[3] << 16),
                          (unsigned)h[4] | ((unsigned)h[5] << 16),
                          (unsigned)h[6] | ((unsigned)h[7] << 16));
    uint4 pl = make_uint4((unsigned)l[0] | ((unsigned)l[1] << 16),
                          (unsigned)l[2] | ((unsigned)l[3] << 16),
                          (unsigned)l[4] | ((unsigned)l[5] << 16),
                          (unsigned)l[6] | ((unsigned)l[7] << 16));
    reinterpret_cast<uint4*>(gBh)[t] = ph;
    reinterpret_cast<uint4*>(gBl)[t] = pl;
}

// ---------------- layer-1 aggregation ------------------------------------------
__global__ void agg1_init_kernel(const float* __restrict__ x) {
    int gid = blockIdx.x * blockDim.x + threadIdx.x;
    if (gid >= NN * 32) return;
    int node = gid >> 5;
    float di = g_deg[node];
    float s = di * di;
    float4 v = reinterpret_cast<const float4*>(x)[gid];
    reinterpret_cast<float4*>(g_agg)[gid] = make_float4(v.x * s, v.y * s, v.z * s, v.w * s);
}
// scatter + fused threefry mask (warp e -> mask words 2e, 2e+1)
__global__ void agg1_scatter_kernel(const float* __restrict__ x,
                                    const int* __restrict__ src,
                                    const int* __restrict__ dst) {
    int gid = blockIdx.x * blockDim.x + threadIdx.x;   // EE*32 threads
    int e = gid >> 5, lane = gid & 31;
    unsigned base = (unsigned)e * 64u + (unsigned)lane;
    unsigned bit0 = tf_bit(base);
    unsigned bit1 = tf_bit(base + 32u);
    unsigned w0 = __ballot_sync(0xFFFFFFFFu, bit0);
    unsigned w1 = __ballot_sync(0xFFFFFFFFu, bit1);
    if (lane == 0) {
        g_mask[2 * e]     = w0;
        g_mask[2 * e + 1] = w1;
    }
    int s = src[e], d = dst[e];
    float nrm = g_deg[s] * g_deg[d];
    float4 v = *reinterpret_cast<const float4*>(&x[s * 128 + lane * 4]);
    red4(&g_agg[d * 128 + lane * 4], v.x * nrm, v.y * nrm, v.z * nrm, v.w * nrm);
}

// ---------------- GEMM1 (mma.sync bf16 3-term): H = relu(AggX@W1+b1)*dropout ---
// CTA tile M=128 x N=128, full K=128 resident in SMEM. 8 warps, warp tile 32x64.
// D = AhBh + AhBl + AlBh (fp32 accumulate); AlBl term dropped (<=2^-18 rel).
#define SROW 136   // padded row stride (bf16 elems) -> conflict-free ldmatrix
__global__ __launch_bounds__(256) void gemm1_mma_kernel(const float* __restrict__ bias,
                                                        float* __restrict__ H) {
    extern __shared__ char dsm[];
    __nv_bfloat16* sAh = reinterpret_cast<__nv_bfloat16*>(dsm);             // 34816B
    __nv_bfloat16* sAl = reinterpret_cast<__nv_bfloat16*>(dsm + 34816);
    __nv_bfloat16* sBh = reinterpret_cast<__nv_bfloat16*>(dsm + 69632);
    __nv_bfloat16* sBl = reinterpret_cast<__nv_bfloat16*>(dsm + 104448);
    __shared__ float sBias[128];

    const int t = threadIdx.x;
    const int lane = t & 31, wid = t >> 5;
    const int m0 = blockIdx.x * 128;
    const int n0 = blockIdx.y * 128;

    if (t < 128) sBias[t] = bias[n0 + t];

    // ---- B tiles: copy gB*[k][n0..n0+127] -> smem [k][SROW] ----
    {
#pragma unroll
        for (int i = 0; i < 8; i++) {
            int c = i * 256 + t;          // 2048 16B-chunks
            int k = c >> 4, c8 = c & 15;  // row k, 8-col chunk
            uint4 vh = *reinterpret_cast<const uint4*>(&gBh[k * 512 + n0 + c8 * 8]);
            uint4 vl = *reinterpret_cast<const uint4*>(&gBl[k * 512 + n0 + c8 * 8]);
            *reinterpret_cast<uint4*>(&sBh[k * SROW + c8 * 8]) = vh;
            *reinterpret_cast<uint4*>(&sBl[k * SROW + c8 * 8]) = vl;
        }
    }
    // ---- A tiles: g_agg fp32 -> bf16 hi/lo split -> smem [m][SROW] ----
    {
        int m = t >> 1, half = t & 1;
        int gr = m0 + m;
#pragma unroll
        for (int kk = 0; kk < 8; kk++) {
            int k = half * 64 + kk * 8;
            unsigned short h[8], l[8];
            if (gr < NN) {
                float4 v0 = *reinterpret_cast<const float4*>(&g_agg[gr * 128 + k]);
                float4 v1 = *reinterpret_cast<const float4*>(&g_agg[gr * 128 + k + 4]);
                float vv[8] = {v0.x, v0.y, v0.z, v0.w, v1.x, v1.y, v1.z, v1.w};
#pragma unroll
                for (int j = 0; j < 8; j++) {
                    __nv_bfloat16 bh = __float2bfloat16(vv[j]);
                    __nv_bfloat16 bl = __float2bfloat16(vv[j] - __bfloat162float(bh));
                    h[j] = *reinterpret_cast<unsigned short*>(&bh);
                    l[j] = *reinterpret_cast<unsigned short*>(&bl);
                }
            } else {
#pragma unroll
                for (int j = 0; j < 8; j++) { h[j] = 0; l[j] = 0; }
            }
            uint4 ph = make_uint4((unsigned)h[0] | ((unsigned)h[1] << 16),
                                  (unsigned)h[2] | ((unsigned)h[3] << 16),
                                  (unsigned)h[4] | ((unsigned)h[5] << 16),
                                  (unsigned)h[6] | ((unsigned)h[7] << 16));
            uint4 pl = make_uint4((unsigned)l[0] | ((unsigned)l[1] << 16),
                                  (unsigned)l[2] | ((unsigned)l[3] << 16),
                                  (unsigned)l[4] | ((unsigned)l[5] << 16),
                                  (unsigned)l[6] | ((unsigned)l[7] << 16));
            *reinterpret_cast<uint4*>(&sAh[m * SROW + k]) = ph;
            *reinterpret_cast<uint4*>(&sAl[m * SROW + k]) = pl;
        }
    }
    __syncthreads();

    // ---- main loop: 8 k-steps of m16n8k16 ----
    const int wm = wid & 3;        // m 32-row block
    const int wn = wid >> 2;       // n 64-col block
    float acc[2][8][4];
#pragma unroll
    for (int mf = 0; mf < 2; mf++)
#pragma unroll
        for (int nf = 0; nf < 8; nf++)
#pragma unroll
            for (int q = 0; q < 4; q++) acc[mf][nf][q] = 0.f;

    // per-lane base addresses (bytes)
    const unsigned aBaseH = smem_u32(sAh) +
        ((unsigned)(wm * 32 + (lane & 15)) * SROW + (unsigned)((lane >> 4) * 8)) * 2u;
    const unsigned aBaseL = aBaseH + 34816u;
    const unsigned bBaseH = smem_u32(sBh) +
        ((unsigned)(lane & 15) * SROW + (unsigned)(wn * 64 + ((lane >> 4) << 3))) * 2u;
    const unsigned bBaseL = bBaseH + 34816u;

#pragma unroll
    for (int ks = 0; ks < 8; ks++) {
        unsigned ah[2][4], al[2][4], bh[4][4], bl[4][4];
#pragma unroll
        for (int mf = 0; mf < 2; mf++) {
            ldsm_x4(ah[mf], aBaseH + (unsigned)(mf * 16 * SROW * 2) + (unsigned)(ks * 32));
            ldsm_x4(al[mf], aBaseL + (unsigned)(mf * 16 * SROW * 2) + (unsigned)(ks * 32));
        }
#pragma unroll
        for (int j = 0; j < 4; j++) {
            ldsm_x4t(bh[j], bBaseH + (unsigned)(ks * 16 * SROW * 2) + (unsigned)(j * 32));
            ldsm_x4t(bl[j], bBaseL + (unsigned)(ks * 16 * SROW * 2) + (unsigned)(j * 32));
        }
#pragma unroll
        for (int mf = 0; mf < 2; mf++) {
#pragma unroll
            for (int j = 0; j < 4; j++) {
                mma_bf16(acc[mf][2 * j],     ah[mf], bh[j][0], bh[j][1]);
                mma_bf16(acc[mf][2 * j],     ah[mf], bl[j][0], bl[j][1]);
                mma_bf16(acc[mf][2 * j],     al[mf], bh[j][0], bh[j][1]);
                mma_bf16(acc[mf][2 * j + 1], ah[mf], bh[j][2], bh[j][3]);
                mma_bf16(acc[mf][2 * j + 1], ah[mf], bl[j][2], bl[j][3]);
                mma_bf16(acc[mf][2 * j + 1], al[mf], bh[j][2], bh[j][3]);
            }
        }
    }

    // ---- epilogue: bias + relu + dropout -> H ----
    const int quad = lane >> 2, qt = lane & 3;
#pragma unroll
    for (int mf = 0; mf < 2; mf++) {
#pragma unroll
        for (int p = 0; p < 2; p++) {
            int row = m0 + wm * 32 + mf * 16 + quad + p * 8;
            if (row >= NN) continue;
            unsigned mw0 = g_mask[row * 16 + ((n0 + wn * 64) >> 5)];
            unsigned mw1 = g_mask[row * 16 + ((n0 + wn * 64) >> 5) + 1];
            float* hp = H + (size_t)row * 512 + n0 + wn * 64;
#pragma unroll
            for (int nf = 0; nf < 8; nf++) {
                int cl = nf * 8 + qt * 2;            // 0..62 within 64-col block
                unsigned mw = (cl < 32) ? mw0 : mw1;
                int sh = cl & 31;
                float v0 = fmaxf(acc[mf][nf][p * 2 + 0] + sBias[wn * 64 + cl + 0], 0.f) * 2.f;
                float v1 = fmaxf(acc[mf][nf][p * 2 + 1] + sBias[wn * 64 + cl + 1], 0.f) * 2.f;
                float2 o;
                o.x = ((mw >> (sh + 0)) & 1u) ? v0 : 0.f;
                o.y = ((mw >> (sh + 1)) & 1u) ? v1 : 0.f;
                *reinterpret_cast<float2*>(hp + cl) = o;
            }
        }
    }
}

// ---------------- GEMM2: g_h2 = H @ W2, fused out-init = b2 + s*h2 -------------
__global__ __launch_bounds__(256) void gemm2_kernel(const float* __restrict__ H,
                                                    const float* __restrict__ W2,
                                                    const float* __restrict__ b2,
                                                    float* __restrict__ out) {
    __shared__ __align__(16) float As[32][260];
    __shared__ __align__(16) float Ws[32][40];
    const int t = threadIdx.x;
    const int rg = t & 63;
    const int cg = t >> 6;
    const int m0 = blockIdx.x * 256;

    unsigned long long acc[4][5];
#pragma unroll
    for (int i = 0; i < 4; i++)
#pragma unroll
        for (int j = 0; j < 5; j++) acc[i][j] = 0ull;

    const int akq = t & 7;
    const int am = t >> 3;

    for (int kc = 0; kc < 16; kc++) {
#pragma unroll
        for (int p = 0; p < 8; p++) {
            int m = p * 32 + am;
            int gr = m0 + m;
            float4 v = make_float4(0.f, 0.f, 0.f, 0.f);
            if (gr < NN)
                v = *reinterpret_cast<const float4*>(&H[gr * 512 + kc * 32 + akq * 4]);
            As[akq * 4 + 0][m] = v.x;
            As[akq * 4 + 1][m] = v.y;
            As[akq * 4 + 2][m] = v.z;
            As[akq * 4 + 3][m] = v.w;
        }
#pragma unroll
        for (int p = 0; p < 2; p++) {
            int idx = p * 256 + t;
            if (idx < 320) {
                int k = idx / 10, c = idx % 10;
                *reinterpret_cast<float4*>(&Ws[k][c * 4]) =
                    *reinterpret_cast<const float4*>(&W2[(kc * 32 + k) * 40 + c * 4]);
            }
        }
        __syncthreads();
#pragma unroll
        for (int k = 0; k < 32; k++) {
            float4 a = *reinterpret_cast<const float4*>(&As[k][rg * 4]);
            const float* wr = &Ws[k][cg * 10];
            unsigned long long w0 = *reinterpret_cast<const unsigned long long*>(wr + 0);
            unsigned long long w1 = *reinterpret_cast<const unsigned long long*>(wr + 2);
            unsigned long long w2 = *reinterpret_cast<const unsigned long long*>(wr + 4);
            unsigned long long w3 = *reinterpret_cast<const unsigned long long*>(wr + 6);
            unsigned long long w4 = *reinterpret_cast<const unsigned long long*>(wr + 8);
            float av[4] = {a.x, a.y, a.z, a.w};
#pragma unroll
            for (int i = 0; i < 4; i++) {
                unsigned long long ai = pack2(av[i], av[i]);
                acc[i][0] = fma2(ai, w0, acc[i][0]);
                acc[i][1] = fma2(ai, w1, acc[i][1]);
                acc[i][2] = fma2(ai, w2, acc[i][2]);
                acc[i][3] = fma2(ai, w3, acc[i][3]);
                acc[i][4] = fma2(ai, w4, acc[i][4]);
            }
        }
        __syncthreads();
    }
#pragma unroll
    for (int i = 0; i < 4; i++) {
        int row = m0 + rg * 4 + i;
        if (row >= NN) continue;
        float di = g_deg[row];
        float s = di * di;
#pragma unroll
        for (int j = 0; j < 5; j++) {
            int c = cg * 10 + j * 2;
            float2 v = *reinterpret_cast<float2*>(&acc[i][j]);
            *reinterpret_cast<unsigned long long*>(&g_h2[row * 40 + c]) = acc[i][j];
            float2 bb = *reinterpret_cast<const float2*>(&b2[c]);
            float2 o = make_float2(bb.x + v.x * s, bb.y + v.y * s);
            *reinterpret_cast<float2*>(&out[row * 40 + c]) = o;
        }
    }
}

// ---------------- layer-2 scatter: out += norm * g_h2[src] ---------------------
__global__ void agg2_scatter_kernel(const int* __restrict__ src,
                                    const int* __restrict__ dst,
                                    float* __restrict__ out) {
    int gid = blockIdx.x * blockDim.x + threadIdx.x;
    int e = gid / 10;
    int c = gid - e * 10;
    if (e >= EE) return;
    int s = src[e], d = dst[e];
    float nrm = g_deg[s] * g_deg[d];
    float4 v = *reinterpret_cast<const float4*>(&g_h2[s * 40 + c * 4]);
    red4(&out[d * 40 + c * 4], v.x * nrm, v.y * nrm, v.z * nrm, v.w * nrm);
}

// ---------------- launch --------------------------------------------------------
extern "C" void kernel_launch(void* const* d_in, const int* in_sizes, int n_in,
                              void* d_out, int out_size) {
    const float* x  = (const float*)d_in[0];
    const int*   ei = (const int*)d_in[1];
    const float* W1 = (const float*)d_in[2];
    const float* b1 = (const float*)d_in[3];
    const float* W2 = (const float*)d_in[4];
    const float* b2 = (const float*)d_in[5];
    (void)in_sizes; (void)n_in; (void)out_size;

    float* out = (float*)d_out;           // [NN, 40]
    float* hidden = out + NN * 40;        // [NN, 512]
    const int* src = ei;
    const int* dst = ei + EE;

    const int GEMM1_SMEM = 139264;        // 4 x 128 x 136 bf16 tiles
    cudaFuncSetAttribute(gemm1_mma_kernel,
                         cudaFuncAttributeMaxDynamicSharedMemorySize, GEMM1_SMEM);

    deg_init_kernel<<<(NN + 255) / 256, 256>>>();
    deg_scatter_kernel<<<(EE + 255) / 256, 256>>>(dst);
    deg_fin_kernel<<<(NN + 255) / 256, 256>>>();

    w1cvt_kernel<<<32, 256>>>(W1);

    agg1_init_kernel<<<(NN * 32) / 256, 256>>>(x);
    agg1_scatter_kernel<<<(EE * 32) / 256, 256>>>(x, src, dst);  // + fused mask

    gemm1_mma_kernel<<<dim3((NN + 127) / 128, 4), 256, GEMM1_SMEM>>>(b1, hidden);
    gemm2_kernel<<<(NN + 255) / 256, 256>>>(hidden, W2, b2, out);

    agg2_scatter_kernel<<<(EE * 10 + 255) / 256, 256>>>(src, dst, out);
}